// round 3
// baseline (speedup 1.0000x reference)
#include <cuda_runtime.h>
#include <cstdint>
#include <math.h>

#define Tn 4096   // B*S tokens
#define Dn 1024
#define Hn 4096
#define En 8
#define NSn 2

// Compact scratch: routed hidden rows sum to exactly 2*Tn (top-2 routing),
// shared experts use NSn*Tn rows. Total (2+NSn)*Tn*Hn floats = 256 MB.
#define ROUTED_ROWS (2 * Tn)
__device__ float g_h[(size_t)(ROUTED_ROWS + NSn * Tn) * Hn];
__device__ int   g_cnt[En];
__device__ int   g_off[En];     // exclusive prefix of g_cnt
__device__ int   g_list[En * Tn];

__device__ __forceinline__ float gelu_f(float v) {
    // jax.nn.gelu default (approximate=True, tanh form)
    float u = 0.7978845608028654f * (v + 0.044715f * v * v * v);
    return 0.5f * v * (1.0f + tanhf(u));
}

__global__ void zero_cnt_kernel() {
    if (threadIdx.x < En) g_cnt[threadIdx.x] = 0;
}

// Exclusive prefix-sum of the 8 counts (single thread; trivial).
__global__ void prefix_kernel() {
    if (threadIdx.x == 0) {
        int s = 0;
#pragma unroll
        for (int e = 0; e < En; e++) { g_off[e] = s; s += g_cnt[e]; }
    }
}

// One block per token: logits = x@Wr + br + gumbel; top-2 (softmax is monotone,
// so top-k of softmax((l+g)/T) == top-2 of (l+g)). Scatter token into expert lists.
__global__ void router_kernel(const float* __restrict__ x,
                              const float* __restrict__ Wr,
                              const float* __restrict__ br,
                              const float* __restrict__ gum) {
    int t = blockIdx.x;
    int tid = threadIdx.x;  // 128 threads
    const float* xr = x + (size_t)t * Dn;
    float acc[En];
#pragma unroll
    for (int e = 0; e < En; e++) acc[e] = 0.f;
    for (int d = tid; d < Dn; d += 128) {
        float xv = xr[d];
        float4 w0 = *(const float4*)(Wr + d * En);
        float4 w1 = *(const float4*)(Wr + d * En + 4);
        acc[0] += xv * w0.x; acc[1] += xv * w0.y;
        acc[2] += xv * w0.z; acc[3] += xv * w0.w;
        acc[4] += xv * w1.x; acc[5] += xv * w1.y;
        acc[6] += xv * w1.z; acc[7] += xv * w1.w;
    }
#pragma unroll
    for (int e = 0; e < En; e++) {
#pragma unroll
        for (int off = 16; off; off >>= 1)
            acc[e] += __shfl_down_sync(0xffffffffu, acc[e], off);
    }
    __shared__ float red[4][En];
    if ((tid & 31) == 0) {
#pragma unroll
        for (int e = 0; e < En; e++) red[tid >> 5][e] = acc[e];
    }
    __syncthreads();
    if (tid == 0) {
        float s[En];
#pragma unroll
        for (int e = 0; e < En; e++)
            s[e] = red[0][e] + red[1][e] + red[2][e] + red[3][e]
                 + br[e] + gum[(size_t)t * En + e];
        int i1 = 0;
#pragma unroll
        for (int e = 1; e < En; e++) if (s[e] > s[i1]) i1 = e;   // ties -> lower idx (matches top_k)
        int i2 = (i1 == 0) ? 1 : 0;
#pragma unroll
        for (int e = 0; e < En; e++)
            if (e != i1 && s[e] > s[i2]) i2 = e;
        int p1 = atomicAdd(&g_cnt[i1], 1); g_list[i1 * Tn + p1] = t;
        int p2 = atomicAdd(&g_cnt[i2], 1); g_list[i2 * Tn + p2] = t;
    }
}

// ---------------- GEMM 1: H[i,:] = gelu(Xg[i,:] @ W1[z] + b1[z]) ----------------
// Tiles: BM=BN=128, BK=16, 256 threads, 8x8 per thread.
// Hidden row for routed expert z, local row r lives at g_h[(g_off[z]+r)*Hn].
// Shared expert z uses rows ROUTED_ROWS + z*Tn + r.
template <bool GATHER>
__global__ void __launch_bounds__(256)
ffn1_k(const float* __restrict__ X, const float* __restrict__ W1,
       const float* __restrict__ b1) {
    const int KD = Dn, ND = Hn;
    int z = blockIdx.z;
    int M = GATHER ? g_cnt[z] : Tn;
    int m0 = blockIdx.y * 128;
    if (m0 >= M) return;
    int n0 = blockIdx.x * 128;
    int tid = threadIdx.x;

    __shared__ __align__(16) float As[16][128];
    __shared__ __align__(16) float Bs[16][128];
    float acc[8][8];
#pragma unroll
    for (int i = 0; i < 8; i++)
#pragma unroll
        for (int j = 0; j < 8; j++) acc[i][j] = 0.f;

    int ar = tid >> 1, ac = (tid & 1) * 8;
    int arow = m0 + ar;
    int grow = 0;
    if (arow < M) grow = GATHER ? g_list[z * Tn + arow] : arow;
    const float* Arow = X + (size_t)grow * KD;
    const float* Bptr = W1 + (size_t)z * KD * ND
                           + (size_t)(tid >> 4) * ND + n0 + (tid & 15) * 8;
    int brw = tid >> 4, bcol = (tid & 15) * 8;
    int tx = tid & 15, ty = tid >> 4;

    for (int k0 = 0; k0 < KD; k0 += 16) {
        float4 a0 = *(const float4*)(Arow + k0 + ac);
        float4 a1 = *(const float4*)(Arow + k0 + ac + 4);
        float4 bb0 = *(const float4*)(Bptr + (size_t)k0 * ND);
        float4 bb1 = *(const float4*)(Bptr + (size_t)k0 * ND + 4);
        As[ac + 0][ar] = a0.x; As[ac + 1][ar] = a0.y;
        As[ac + 2][ar] = a0.z; As[ac + 3][ar] = a0.w;
        As[ac + 4][ar] = a1.x; As[ac + 5][ar] = a1.y;
        As[ac + 6][ar] = a1.z; As[ac + 7][ar] = a1.w;
        *(float4*)&Bs[brw][bcol]     = bb0;
        *(float4*)&Bs[brw][bcol + 4] = bb1;
        __syncthreads();
#pragma unroll
        for (int kk = 0; kk < 16; kk++) {
            float a[8], b[8];
            *(float4*)&a[0] = *(const float4*)&As[kk][ty * 8];
            *(float4*)&a[4] = *(const float4*)&As[kk][ty * 8 + 4];
            *(float4*)&b[0] = *(const float4*)&Bs[kk][tx * 8];
            *(float4*)&b[4] = *(const float4*)&Bs[kk][tx * 8 + 4];
#pragma unroll
            for (int i = 0; i < 8; i++)
#pragma unroll
                for (int j = 0; j < 8; j++) acc[i][j] += a[i] * b[j];
        }
        __syncthreads();
    }

    size_t rowBase = GATHER ? (size_t)g_off[z] : (size_t)(ROUTED_ROWS + z * Tn);
    const float* bz = b1 + (size_t)z * ND + n0 + tx * 8;
#pragma unroll
    for (int i = 0; i < 8; i++) {
        int r = m0 + ty * 8 + i;
        if (r < M) {
            float* hr = g_h + (rowBase + r) * Hn + n0 + tx * 8;
#pragma unroll
            for (int j = 0; j < 8; j++) hr[j] = gelu_f(acc[i][j] + bz[j]);
        }
    }
}

// ---------------- GEMM 2: out[tok,:] += H[i,:] @ W2[z] + b2[z] ----------------
template <bool GATHER>
__global__ void __launch_bounds__(256)
ffn2_k(const float* __restrict__ W2, const float* __restrict__ b2,
       float* __restrict__ out) {
    const int KD = Hn, ND = Dn;
    int z = blockIdx.z;
    int M = GATHER ? g_cnt[z] : Tn;
    int m0 = blockIdx.y * 128;
    if (m0 >= M) return;
    int n0 = blockIdx.x * 128;
    int tid = threadIdx.x;

    __shared__ __align__(16) float As[16][128];
    __shared__ __align__(16) float Bs[16][128];
    float acc[8][8];
#pragma unroll
    for (int i = 0; i < 8; i++)
#pragma unroll
        for (int j = 0; j < 8; j++) acc[i][j] = 0.f;

    size_t rowBase = GATHER ? (size_t)g_off[z] : (size_t)(ROUTED_ROWS + z * Tn);
    const float* X = g_h + rowBase * Hn;
    int ar = tid >> 1, ac = (tid & 1) * 8;
    int arow = m0 + ar;
    int r_ld = (arow < M) ? arow : 0;
    const float* Arow = X + (size_t)r_ld * KD;
    const float* Bptr = W2 + (size_t)z * KD * ND
                           + (size_t)(tid >> 4) * ND + n0 + (tid & 15) * 8;
    int brw = tid >> 4, bcol = (tid & 15) * 8;
    int tx = tid & 15, ty = tid >> 4;

    for (int k0 = 0; k0 < KD; k0 += 16) {
        float4 a0 = *(const float4*)(Arow + k0 + ac);
        float4 a1 = *(const float4*)(Arow + k0 + ac + 4);
        float4 bb0 = *(const float4*)(Bptr + (size_t)k0 * ND);
        float4 bb1 = *(const float4*)(Bptr + (size_t)k0 * ND + 4);
        As[ac + 0][ar] = a0.x; As[ac + 1][ar] = a0.y;
        As[ac + 2][ar] = a0.z; As[ac + 3][ar] = a0.w;
        As[ac + 4][ar] = a1.x; As[ac + 5][ar] = a1.y;
        As[ac + 6][ar] = a1.z; As[ac + 7][ar] = a1.w;
        *(float4*)&Bs[brw][bcol]     = bb0;
        *(float4*)&Bs[brw][bcol + 4] = bb1;
        __syncthreads();
#pragma unroll
        for (int kk = 0; kk < 16; kk++) {
            float a[8], b[8];
            *(float4*)&a[0] = *(const float4*)&As[kk][ty * 8];
            *(float4*)&a[4] = *(const float4*)&As[kk][ty * 8 + 4];
            *(float4*)&b[0] = *(const float4*)&Bs[kk][tx * 8];
            *(float4*)&b[4] = *(const float4*)&Bs[kk][tx * 8 + 4];
#pragma unroll
            for (int i = 0; i < 8; i++)
#pragma unroll
                for (int j = 0; j < 8; j++) acc[i][j] += a[i] * b[j];
        }
        __syncthreads();
    }

    const float* bz = b2 + (size_t)z * ND + n0 + tx * 8;
#pragma unroll
    for (int i = 0; i < 8; i++) {
        int r = m0 + ty * 8 + i;
        if (r < M) {
            int g = GATHER ? g_list[z * Tn + r] : r;
            float* orow = out + (size_t)g * Dn + n0 + tx * 8;
#pragma unroll
            for (int j = 0; j < 8; j++)
                atomicAdd(&orow[j], acc[i][j] + bz[j]);
        }
    }
}

extern "C" void kernel_launch(void* const* d_in, const int* in_sizes, int n_in,
                              void* d_out, int out_size) {
    const float* x   = (const float*)d_in[0];
    const float* Ws1 = (const float*)d_in[1];
    const float* bs1 = (const float*)d_in[2];
    const float* Ws2 = (const float*)d_in[3];
    const float* bs2 = (const float*)d_in[4];
    const float* We1 = (const float*)d_in[5];
    const float* be1 = (const float*)d_in[6];
    const float* We2 = (const float*)d_in[7];
    const float* be2 = (const float*)d_in[8];
    const float* Wr  = (const float*)d_in[9];
    const float* br  = (const float*)d_in[10];
    const float* gum = (const float*)d_in[11];
    float* out = (float*)d_out;

    cudaMemsetAsync(out, 0, (size_t)out_size * sizeof(float), 0);
    zero_cnt_kernel<<<1, 32>>>();
    router_kernel<<<Tn, 128>>>(x, Wr, br, gum);
    prefix_kernel<<<1, 32>>>();

    // Routed experts: only selected tokens (gathered). Grid covers worst case;
    // blocks beyond the runtime count exit immediately.
    ffn1_k<true><<<dim3(Hn / 128, Tn / 128, En), 256>>>(x, We1, be1);
    ffn2_k<true><<<dim3(Dn / 128, Tn / 128, En), 256>>>(We2, be2, out);

    // Shared experts: dense over all tokens.
    ffn1_k<false><<<dim3(Hn / 128, Tn / 128, NSn), 256>>>(x, Ws1, bs1);
    ffn2_k<false><<<dim3(Dn / 128, Tn / 128, NSn), 256>>>(Ws2, bs2, out);
}